// round 4
// baseline (speedup 1.0000x reference)
#include <cuda_runtime.h>
#include <cuda_bf16.h>
#include <math.h>
#include <stdint.h>

#define NROWS 8192
#define NC    256
#define NWORDS (NC/2)          // 128 uint32 (bf16x2) per row

// ---------------- scratch ----------------------------------------------------
__device__ float    g_nrm[4][NROWS * NC];      // normalized fp32 (v,t,pv,pt)
__device__ unsigned g_bhi[4][NROWS * NWORDS];  // bf16 hi, packed bf16x2
__device__ unsigned g_blo[4][NROWS * NWORDS];  // bf16 lo, packed bf16x2
__device__ float    g_d1[NROWS];               // v_i . pt_i
__device__ float    g_d2[NROWS];               // t_i . pv_i
__device__ float    g_cs[4][64][NC];
__device__ float    g_cq[4][64][NC];

// ---------------- small helpers ----------------------------------------------
__device__ __forceinline__ uint32_t smem_u32(const void* p) {
    uint32_t a;
    asm("{ .reg .u64 t; cvta.to.shared.u64 t, %1; cvt.u32.u64 %0, t; }"
        : "=r"(a) : "l"(p));
    return a;
}

#define CP_ASYNC16(dst, src)                                                   \
    asm volatile("cp.async.cg.shared.global [%0], [%1], 16;"                   \
                 :: "r"(dst), "l"(src) : "memory")
#define CP_COMMIT()  asm volatile("cp.async.commit_group;" ::: "memory")
#define CP_WAIT2()   asm volatile("cp.async.wait_group 2;" ::: "memory")
#define CP_WAIT0()   asm volatile("cp.async.wait_group 0;" ::: "memory")

#define LDSM_X4(r0, r1, r2, r3, addr)                                          \
    asm volatile("ldmatrix.sync.aligned.m8n8.x4.shared.b16 {%0,%1,%2,%3}, [%4];" \
                 : "=r"(r0), "=r"(r1), "=r"(r2), "=r"(r3) : "r"(addr))

#define MMA16816(d, a, b0, b1)                                                 \
    asm volatile("mma.sync.aligned.m16n8k16.row.col.f32.bf16.bf16.f32 "        \
                 "{%0,%1,%2,%3}, {%4,%5,%6,%7}, {%8,%9}, {%0,%1,%2,%3};"       \
                 : "+f"((d)[0]), "+f"((d)[1]), "+f"((d)[2]), "+f"((d)[3])      \
                 : "r"((a)[0]), "r"((a)[1]), "r"((a)[2]), "r"((a)[3]),         \
                   "r"(b0), "r"(b1))

// ---------------- 1. normalize + bf16 hi/lo split ---------------------------
__device__ __forceinline__ unsigned pack2(__nv_bfloat16 a, __nv_bfloat16 b) {
    return (unsigned)__bfloat16_as_ushort(a) | ((unsigned)__bfloat16_as_ushort(b) << 16);
}
__device__ __forceinline__ void split_pair(float a, float b, unsigned& hi, unsigned& lo) {
    __nv_bfloat16 ha = __float2bfloat16_rn(a), hb = __float2bfloat16_rn(b);
    float ra = a - __bfloat162float(ha);
    float rb = b - __bfloat162float(hb);
    hi = pack2(ha, hb);
    lo = pack2(__float2bfloat16_rn(ra), __float2bfloat16_rn(rb));
}

__global__ void normalize_kernel(const float* __restrict__ v,
                                 const float* __restrict__ t,
                                 const float* __restrict__ pv,
                                 const float* __restrict__ pt) {
    int y = blockIdx.y;
    const float* src = (y == 0) ? v : (y == 1) ? t : (y == 2) ? pv : pt;
    int warp = threadIdx.x >> 5, lane = threadIdx.x & 31;
    int row = blockIdx.x * 8 + warp;
    const float4* s4 = (const float4*)(src + (size_t)row * NC);
    float4 x0 = s4[lane];
    float4 x1 = s4[lane + 32];
    float ss = x0.x*x0.x + x0.y*x0.y + x0.z*x0.z + x0.w*x0.w
             + x1.x*x1.x + x1.y*x1.y + x1.z*x1.z + x1.w*x1.w;
    #pragma unroll
    for (int o = 16; o; o >>= 1) ss += __shfl_xor_sync(0xffffffffu, ss, o);
    float r = 1.0f / fmaxf(sqrtf(ss), 1e-12f);
    x0.x *= r; x0.y *= r; x0.z *= r; x0.w *= r;
    x1.x *= r; x1.y *= r; x1.z *= r; x1.w *= r;
    float4* d4 = (float4*)(g_nrm[y] + (size_t)row * NC);
    d4[lane] = x0;
    d4[lane + 32] = x1;
    unsigned h, l;
    size_t rb = (size_t)row * NWORDS;
    split_pair(x0.x, x0.y, h, l); g_bhi[y][rb + 2*lane]      = h; g_blo[y][rb + 2*lane]      = l;
    split_pair(x0.z, x0.w, h, l); g_bhi[y][rb + 2*lane + 1]  = h; g_blo[y][rb + 2*lane + 1]  = l;
    split_pair(x1.x, x1.y, h, l); g_bhi[y][rb + 64 + 2*lane] = h; g_blo[y][rb + 64 + 2*lane] = l;
    split_pair(x1.z, x1.w, h, l); g_bhi[y][rb + 65 + 2*lane] = h; g_blo[y][rb + 65 + 2*lane] = l;
}

// ---------------- 2. per-column partial sums --------------------------------
__global__ void colstats_kernel() {
    const float* X = g_nrm[blockIdx.y];
    int col = threadIdx.x;
    int r0 = blockIdx.x * 128;
    float s = 0.f, q = 0.f;
    #pragma unroll 4
    for (int r = 0; r < 128; r++) {
        float x = X[(size_t)(r0 + r) * NC + col];
        s += x; q += x * x;
    }
    g_cs[blockIdx.y][blockIdx.x][col] = s;
    g_cq[blockIdx.y][blockIdx.x][col] = q;
}

// ---------------- 3. diagonals -----------------------------------------------
__global__ void diag_kernel() {
    int warp = threadIdx.x >> 5, lane = threadIdx.x & 31;
    int row = blockIdx.x * 8 + warp;
    size_t base = (size_t)row * NC;
    const float4* a = (const float4*)(g_nrm[0] + base);
    const float4* b = (const float4*)(g_nrm[3] + base);
    const float4* c = (const float4*)(g_nrm[1] + base);
    const float4* d = (const float4*)(g_nrm[2] + base);
    float4 a0 = a[lane], a1 = a[lane+32], b0 = b[lane], b1 = b[lane+32];
    float4 c0 = c[lane], c1 = c[lane+32], d0 = d[lane], d1 = d[lane+32];
    float s1 = a0.x*b0.x + a0.y*b0.y + a0.z*b0.z + a0.w*b0.w
             + a1.x*b1.x + a1.y*b1.y + a1.z*b1.z + a1.w*b1.w;
    float s2 = c0.x*d0.x + c0.y*d0.y + c0.z*d0.z + c0.w*d0.w
             + c1.x*d1.x + c1.y*d1.y + c1.z*d1.z + c1.w*d1.w;
    #pragma unroll
    for (int o = 16; o; o >>= 1) {
        s1 += __shfl_xor_sync(0xffffffffu, s1, o);
        s2 += __shfl_xor_sync(0xffffffffu, s2, o);
    }
    if (lane == 0) { g_d1[row] = s1; g_d2[row] = s2; }
}

// ---------------- 4. HMMA GEMM + rank count ---------------------------------
// 3-term split GEMM, K'=768. BM=BN=128, BK=64. 512 threads, 16 warps (4x4),
// warp tile 32x32. 4-stage cp.async pipeline, ONE syncthreads per chunk.
#define STAGE_B  32768              // A 16KB + B 16KB
#define STAGES   4
#define DYN_SMEM (STAGES * STAGE_B + 1024)
#define NCHUNK   12                 // 768 / 64
#define TOTAL    (64 * NCHUNK)

__global__ void __launch_bounds__(512, 1) count_kernel(float* __restrict__ out) {
    extern __shared__ char dynsm[];
    __shared__ int scnt[128];

    const int t = threadIdx.x;
    const int lane = t & 31;
    const int wid = t >> 5;
    const int warp_m = wid & 3;          // 0..3 -> 32-row slab
    const int warp_n = wid >> 2;         // 0..3 -> 32-col slab
    const int mat = blockIdx.y;
    const int i0 = blockIdx.x * 128;

    const unsigned* __restrict__ Ahi = g_bhi[mat ? 1 : 0];
    const unsigned* __restrict__ Alo = g_blo[mat ? 1 : 0];
    const unsigned* __restrict__ Bhi = g_bhi[mat ? 2 : 3];
    const unsigned* __restrict__ Blo = g_blo[mat ? 2 : 3];
    const float*    __restrict__ diag = mat ? g_d2 : g_d1;
    float* __restrict__ mrk = out + 5 + (size_t)(mat ? 7 : 3) * NROWS;

    const unsigned sb = (smem_u32(dynsm) + 1023u) & ~1023u;

    if (t < 128) scnt[t] = 0;

    // loader: 512 threads, each does 2 A rows + 2 B rows (16B each)
    const int lg_r = t >> 3;             // 0..63
    const int lg_q = t & 7;              // 16B quad within 128B row
    const unsigned sw0 = (lg_r * 128) + (((unsigned)(lg_q ^ (lg_r & 7))) << 4);
    const unsigned sw1 = ((lg_r + 64) * 128) + (((unsigned)(lg_q ^ ((lg_r + 64) & 7))) << 4);
    const size_t gA0 = (size_t)(i0 + lg_r) * NWORDS + lg_q * 4;
    const size_t gA1 = gA0 + (size_t)64 * NWORDS;
    const size_t gB0 = (size_t)lg_r * NWORDS + lg_q * 4;
    const size_t gB1 = gB0 + (size_t)64 * NWORDS;

    // per-thread diag values and counters
    float dva[2], dvb[2];
    #pragma unroll
    for (int mt = 0; mt < 2; mt++) {
        int ra = i0 + warp_m * 32 + mt * 16 + (lane >> 2);
        dva[mt] = diag[ra];
        dvb[mt] = diag[ra + 8];
    }
    int cnt[2][2];
    #pragma unroll
    for (int mt = 0; mt < 2; mt++) { cnt[mt][0] = 0; cnt[mt][1] = 0; }

    // ldmatrix address components (within a stage)
    unsigned offA[2], permA[2];
    #pragma unroll
    for (int mt = 0; mt < 2; mt++) {
        int rowA = warp_m * 32 + mt * 16 + (lane & 15);
        offA[mt] = rowA * 128;
        permA[mt] = (rowA & 7);
    }
    const unsigned halfA = lane >> 4;
    unsigned offB[2], permB[2];
    #pragma unroll
    for (int np = 0; np < 2; np++) {
        int rowB = warp_n * 32 + np * 16 + ((lane & 16) >> 1) + (lane & 7);
        offB[np] = 16384 + rowB * 128;
        permB[np] = (rowB & 7);
    }
    const unsigned halfB = (lane >> 3) & 1;

    float acc[2][4][4];
    #pragma unroll
    for (int mt = 0; mt < 2; mt++)
        #pragma unroll
        for (int nt = 0; nt < 4; nt++)
            #pragma unroll
            for (int c = 0; c < 4; c++) acc[mt][nt][c] = 0.f;

    // ---- stage issue helper ----
    auto issue = [&](int idx) {
        int jt  = idx / NCHUNK;
        int kc  = idx - jt * NCHUNK;
        int term = kc >> 2;
        int kbw  = (kc & 3) * 32;
        const unsigned* Asrc = (term < 2) ? Ahi : Alo;
        const unsigned* Bsrc = (term == 1) ? Blo : Bhi;
        size_t jb = (size_t)jt * 128 * NWORDS;
        unsigned st = sb + (unsigned)(idx & (STAGES - 1)) * STAGE_B;
        CP_ASYNC16(st + sw0,         __cvta_generic_to_global(Asrc + gA0 + kbw));
        CP_ASYNC16(st + sw1,         __cvta_generic_to_global(Asrc + gA1 + kbw));
        CP_ASYNC16(st + 16384 + sw0, __cvta_generic_to_global(Bsrc + jb + gB0 + kbw));
        CP_ASYNC16(st + 16384 + sw1, __cvta_generic_to_global(Bsrc + jb + gB1 + kbw));
    };

    // prologue: stages 0..2 in flight
    #pragma unroll
    for (int s = 0; s < STAGES - 1; s++) { issue(s); CP_COMMIT(); }

    for (int idx = 0; idx < TOTAL; idx++) {
        const int jt = idx / NCHUNK;
        const int kc = idx - jt * NCHUNK;

        CP_WAIT2();              // stage idx resident
        __syncthreads();         // all warps done with buffer (idx-1)%4

        if (idx + STAGES - 1 < TOTAL) issue(idx + STAGES - 1);
        CP_COMMIT();

        // ---- compute chunk idx: 4 k-steps of 16 ----
        const unsigned base = sb + (unsigned)(idx & (STAGES - 1)) * STAGE_B;
        #pragma unroll
        for (int ks = 0; ks < 4; ks++) {
            unsigned a[2][4], b[2][4];
            #pragma unroll
            for (int mt = 0; mt < 2; mt++) {
                unsigned addr = base + offA[mt]
                              + (((2u * ks + halfA) ^ permA[mt]) << 4);
                LDSM_X4(a[mt][0], a[mt][1], a[mt][2], a[mt][3], addr);
            }
            #pragma unroll
            for (int np = 0; np < 2; np++) {
                unsigned addr = base + offB[np]
                              + (((2u * ks + halfB) ^ permB[np]) << 4);
                LDSM_X4(b[np][0], b[np][1], b[np][2], b[np][3], addr);
            }
            #pragma unroll
            for (int mt = 0; mt < 2; mt++) {
                #pragma unroll
                for (int nt = 0; nt < 4; nt++) {
                    int np = nt >> 1, o = (nt & 1) * 2;
                    MMA16816(acc[mt][nt], a[mt], b[np][o], b[np][o + 1]);
                }
            }
        }

        // ---- end of j-tile: compare + fold ----
        if (kc == NCHUNK - 1) {
            int j0 = jt * 128 + warp_n * 32 + (lane & 3) * 2;
            #pragma unroll
            for (int mt = 0; mt < 2; mt++) {
                int ia = i0 + warp_m * 32 + mt * 16 + (lane >> 2);
                int ib = ia + 8;
                float da = dva[mt], db = dvb[mt];
                int ca = 0, cb = 0;
                #pragma unroll
                for (int nt = 0; nt < 4; nt++) {
                    int j = j0 + nt * 8;
                    float s0 = acc[mt][nt][0], s1 = acc[mt][nt][1];
                    float s2 = acc[mt][nt][2], s3 = acc[mt][nt][3];
                    ca += (j     != ia) && ((s0 > da) || (s0 == da && j     < ia));
                    ca += (j + 1 != ia) && ((s1 > da) || (s1 == da && j + 1 < ia));
                    cb += (j     != ib) && ((s2 > db) || (s2 == db && j     < ib));
                    cb += (j + 1 != ib) && ((s3 > db) || (s3 == db && j + 1 < ib));
                    acc[mt][nt][0] = 0.f; acc[mt][nt][1] = 0.f;
                    acc[mt][nt][2] = 0.f; acc[mt][nt][3] = 0.f;
                }
                cnt[mt][0] += ca;
                cnt[mt][1] += cb;
            }
        }
    }

    // ---- reduce counters ----
    __syncthreads();
    #pragma unroll
    for (int mt = 0; mt < 2; mt++) {
        int la = warp_m * 32 + mt * 16 + (lane >> 2);
        atomicAdd(&scnt[la], cnt[mt][0]);
        atomicAdd(&scnt[la + 8], cnt[mt][1]);
    }
    __syncthreads();
    if (t < 128) mrk[i0 + t] = (float)scnt[t];
}

// ---------------- 5. scalars -------------------------------------------------
__global__ void finalize_kernel(float* __restrict__ out) {
    __shared__ float red[256];
    int t = threadIdx.x;
    for (int m = 0; m < 4; m++) {
        float s = 0.f, q = 0.f;
        #pragma unroll 8
        for (int ch = 0; ch < 64; ch++) { s += g_cs[m][ch][t]; q += g_cq[m][ch][t]; }
        float var = (q - s * s / (float)NROWS) / (float)(NROWS - 1);
        red[t] = sqrtf(fmaxf(var, 0.f));
        __syncthreads();
        for (int off = 128; off; off >>= 1) {
            if (t < off) red[t] += red[t + off];
            __syncthreads();
        }
        if (t == 0) out[1 + m] = red[0] / (float)NC;
        __syncthreads();
    }
    float s1 = 0.f, s2 = 0.f;
    for (int i = t; i < NROWS; i += 256) { s1 += g_d1[i]; s2 += g_d2[i]; }
    red[t] = s1; __syncthreads();
    for (int off = 128; off; off >>= 1) { if (t < off) red[t] += red[t + off]; __syncthreads(); }
    float S1 = red[0]; __syncthreads();
    red[t] = s2; __syncthreads();
    for (int off = 128; off; off >>= 1) { if (t < off) red[t] += red[t + off]; __syncthreads(); }
    if (t == 0) {
        float S2 = red[0];
        out[0] = -0.5f * (S1 / (float)NROWS) - 0.5f * (S2 / (float)NROWS);
    }
}

// ---------------- 6. constant recall vectors --------------------------------
__global__ void fill_kernel(float* __restrict__ out) {
    int idx = blockIdx.x * 256 + threadIdx.x;
    if (idx >= 3 * NROWS) return;
    int r = idx / NROWS;
    float val = (r == 0) ? 1.0f : (r == 1) ? 5.0f : 10.0f;
    out[5 + idx] = val;
    out[5 + 4 * NROWS + idx] = val;
}

// ---------------- launch -----------------------------------------------------
extern "C" void kernel_launch(void* const* d_in, const int* in_sizes, int n_in,
                              void* d_out, int out_size) {
    const float* v  = (const float*)d_in[0];
    const float* t  = (const float*)d_in[1];
    const float* pv = (const float*)d_in[2];
    const float* pt = (const float*)d_in[3];
    float* out = (float*)d_out;

    cudaFuncSetAttribute(count_kernel,
                         cudaFuncAttributeMaxDynamicSharedMemorySize, DYN_SMEM);

    normalize_kernel<<<dim3(NROWS / 8, 4), 256>>>(v, t, pv, pt);
    colstats_kernel<<<dim3(64, 4), 256>>>();
    diag_kernel<<<dim3(NROWS / 8), 256>>>();
    count_kernel<<<dim3(64, 2), 512, DYN_SMEM>>>(out);
    finalize_kernel<<<1, 256>>>(out);
    fill_kernel<<<(3 * NROWS + 255) / 256, 256>>>(out);
}

// round 5
// speedup vs baseline: 1.1622x; 1.1622x over previous
#include <cuda_runtime.h>
#include <cuda_bf16.h>
#include <math.h>
#include <stdint.h>

#define NROWS 8192
#define NC    256
#define NWORDS (NC/2)          // 128 uint32 (bf16x2) per row

// ---------------- scratch ----------------------------------------------------
__device__ float    g_nrm[4][NROWS * NC];      // normalized fp32 (v,t,pv,pt)
__device__ unsigned g_bhi[4][NROWS * NWORDS];  // bf16 hi, packed bf16x2
__device__ unsigned g_blo[4][NROWS * NWORDS];  // bf16 lo, packed bf16x2
__device__ float    g_d1[NROWS];               // v_i . pt_i
__device__ float    g_d2[NROWS];               // t_i . pv_i
__device__ float    g_cs[4][64][NC];
__device__ float    g_cq[4][64][NC];

// ---------------- small helpers ----------------------------------------------
__device__ __forceinline__ uint32_t smem_u32(const void* p) {
    uint32_t a;
    asm("{ .reg .u64 t; cvta.to.shared.u64 t, %1; cvt.u32.u64 %0, t; }"
        : "=r"(a) : "l"(p));
    return a;
}

#define CP_ASYNC16(dst, src)                                                   \
    asm volatile("cp.async.cg.shared.global [%0], [%1], 16;"                   \
                 :: "r"(dst), "l"(src) : "memory")
#define CP_COMMIT()  asm volatile("cp.async.commit_group;" ::: "memory")
#define CP_WAIT1()   asm volatile("cp.async.wait_group 1;" ::: "memory")
#define CP_WAIT0()   asm volatile("cp.async.wait_group 0;" ::: "memory")

#define LDSM_X4(r0, r1, r2, r3, addr)                                          \
    asm volatile("ldmatrix.sync.aligned.m8n8.x4.shared.b16 {%0,%1,%2,%3}, [%4];" \
                 : "=r"(r0), "=r"(r1), "=r"(r2), "=r"(r3) : "r"(addr))

#define MMA16816(d, a, b0, b1)                                                 \
    asm volatile("mma.sync.aligned.m16n8k16.row.col.f32.bf16.bf16.f32 "        \
                 "{%0,%1,%2,%3}, {%4,%5,%6,%7}, {%8,%9}, {%0,%1,%2,%3};"       \
                 : "+f"((d)[0]), "+f"((d)[1]), "+f"((d)[2]), "+f"((d)[3])      \
                 : "r"((a)[0]), "r"((a)[1]), "r"((a)[2]), "r"((a)[3]),         \
                   "r"(b0), "r"(b1))

// ---------------- 1. normalize + bf16 hi/lo split ---------------------------
__device__ __forceinline__ unsigned pack2(__nv_bfloat16 a, __nv_bfloat16 b) {
    return (unsigned)__bfloat16_as_ushort(a) | ((unsigned)__bfloat16_as_ushort(b) << 16);
}
__device__ __forceinline__ void split_pair(float a, float b, unsigned& hi, unsigned& lo) {
    __nv_bfloat16 ha = __float2bfloat16_rn(a), hb = __float2bfloat16_rn(b);
    float ra = a - __bfloat162float(ha);
    float rb = b - __bfloat162float(hb);
    hi = pack2(ha, hb);
    lo = pack2(__float2bfloat16_rn(ra), __float2bfloat16_rn(rb));
}

__global__ void normalize_kernel(const float* __restrict__ v,
                                 const float* __restrict__ t,
                                 const float* __restrict__ pv,
                                 const float* __restrict__ pt) {
    int y = blockIdx.y;
    const float* src = (y == 0) ? v : (y == 1) ? t : (y == 2) ? pv : pt;
    int warp = threadIdx.x >> 5, lane = threadIdx.x & 31;
    int row = blockIdx.x * 8 + warp;
    const float4* s4 = (const float4*)(src + (size_t)row * NC);
    float4 x0 = s4[lane];
    float4 x1 = s4[lane + 32];
    float ss = x0.x*x0.x + x0.y*x0.y + x0.z*x0.z + x0.w*x0.w
             + x1.x*x1.x + x1.y*x1.y + x1.z*x1.z + x1.w*x1.w;
    #pragma unroll
    for (int o = 16; o; o >>= 1) ss += __shfl_xor_sync(0xffffffffu, ss, o);
    float r = 1.0f / fmaxf(sqrtf(ss), 1e-12f);
    x0.x *= r; x0.y *= r; x0.z *= r; x0.w *= r;
    x1.x *= r; x1.y *= r; x1.z *= r; x1.w *= r;
    float4* d4 = (float4*)(g_nrm[y] + (size_t)row * NC);
    d4[lane] = x0;
    d4[lane + 32] = x1;
    unsigned h, l;
    size_t rb = (size_t)row * NWORDS;
    split_pair(x0.x, x0.y, h, l); g_bhi[y][rb + 2*lane]      = h; g_blo[y][rb + 2*lane]      = l;
    split_pair(x0.z, x0.w, h, l); g_bhi[y][rb + 2*lane + 1]  = h; g_blo[y][rb + 2*lane + 1]  = l;
    split_pair(x1.x, x1.y, h, l); g_bhi[y][rb + 64 + 2*lane] = h; g_blo[y][rb + 64 + 2*lane] = l;
    split_pair(x1.z, x1.w, h, l); g_bhi[y][rb + 65 + 2*lane] = h; g_blo[y][rb + 65 + 2*lane] = l;
}

// ---------------- 2. per-column partial sums --------------------------------
__global__ void colstats_kernel() {
    const float* X = g_nrm[blockIdx.y];
    int col = threadIdx.x;
    int r0 = blockIdx.x * 128;
    float s = 0.f, q = 0.f;
    #pragma unroll 4
    for (int r = 0; r < 128; r++) {
        float x = X[(size_t)(r0 + r) * NC + col];
        s += x; q += x * x;
    }
    g_cs[blockIdx.y][blockIdx.x][col] = s;
    g_cq[blockIdx.y][blockIdx.x][col] = q;
}

// ---------------- 3. diagonals -----------------------------------------------
__global__ void diag_kernel() {
    int warp = threadIdx.x >> 5, lane = threadIdx.x & 31;
    int row = blockIdx.x * 8 + warp;
    size_t base = (size_t)row * NC;
    const float4* a = (const float4*)(g_nrm[0] + base);
    const float4* b = (const float4*)(g_nrm[3] + base);
    const float4* c = (const float4*)(g_nrm[1] + base);
    const float4* d = (const float4*)(g_nrm[2] + base);
    float4 a0 = a[lane], a1 = a[lane+32], b0 = b[lane], b1 = b[lane+32];
    float4 c0 = c[lane], c1 = c[lane+32], d0 = d[lane], d1 = d[lane+32];
    float s1 = a0.x*b0.x + a0.y*b0.y + a0.z*b0.z + a0.w*b0.w
             + a1.x*b1.x + a1.y*b1.y + a1.z*b1.z + a1.w*b1.w;
    float s2 = c0.x*d0.x + c0.y*d0.y + c0.z*d0.z + c0.w*d0.w
             + c1.x*d1.x + c1.y*d1.y + c1.z*d1.z + c1.w*d1.w;
    #pragma unroll
    for (int o = 16; o; o >>= 1) {
        s1 += __shfl_xor_sync(0xffffffffu, s1, o);
        s2 += __shfl_xor_sync(0xffffffffu, s2, o);
    }
    if (lane == 0) { g_d1[row] = s1; g_d2[row] = s2; }
}

// ---------------- 4. HMMA GEMM + rank count ---------------------------------
// 3-term split GEMM, K'=768. BM=128, BN=256, BK=64. 256 threads, 8 warps (2x4),
// warp tile 64x64 (max fragment reuse -> smem traffic 128 B/MMA).
// 3-stage cp.async pipeline, one syncthreads per chunk.
#define A_BYTES  16384              // 128 rows x 128 B
#define B_BYTES  32768              // 256 rows x 128 B
#define STAGE_B  (A_BYTES + B_BYTES)
#define STAGES   3
#define DYN_SMEM (STAGES * STAGE_B + 1024)
#define NCHUNK   12                 // 768 / 64
#define NJT      32                 // 8192 / 256
#define TOTAL    (NJT * NCHUNK)

__global__ void __launch_bounds__(256, 1) count_kernel(float* __restrict__ out) {
    extern __shared__ char dynsm[];
    __shared__ int scnt[128];

    const int t = threadIdx.x;
    const int lane = t & 31;
    const int wid = t >> 5;
    const int warp_m = wid & 1;          // 0..1 -> 64-row slab
    const int warp_n = wid >> 1;         // 0..3 -> 64-col slab
    const int mat = blockIdx.y;
    const int i0 = blockIdx.x * 128;

    const unsigned* __restrict__ Ahi = g_bhi[mat ? 1 : 0];
    const unsigned* __restrict__ Alo = g_blo[mat ? 1 : 0];
    const unsigned* __restrict__ Bhi = g_bhi[mat ? 2 : 3];
    const unsigned* __restrict__ Blo = g_blo[mat ? 2 : 3];
    const float*    __restrict__ diag = mat ? g_d2 : g_d1;
    float* __restrict__ mrk = out + 5 + (size_t)(mat ? 7 : 3) * NROWS;

    const unsigned sb = (smem_u32(dynsm) + 1023u) & ~1023u;

    if (t < 128) scnt[t] = 0;

    // loader: 256 threads. A: 128 rows (4/thread), B: 256 rows (8/thread), 16B each
    const int lg_r = t >> 3;             // 0..31
    const int lg_q = t & 7;              // 16B quad within 128B row
    const unsigned swq = ((unsigned)(lg_q ^ (lg_r & 7))) << 4;   // same for r+32k

    // per-thread diag values and counters
    float dva[4], dvb[4];
    #pragma unroll
    for (int mt = 0; mt < 4; mt++) {
        int ra = i0 + warp_m * 64 + mt * 16 + (lane >> 2);
        dva[mt] = diag[ra];
        dvb[mt] = diag[ra + 8];
    }
    int cnt[4][2];
    #pragma unroll
    for (int mt = 0; mt < 4; mt++) { cnt[mt][0] = 0; cnt[mt][1] = 0; }

    // ldmatrix address components (within a stage)
    unsigned offA[4], permA[4];
    #pragma unroll
    for (int mt = 0; mt < 4; mt++) {
        int rowA = warp_m * 64 + mt * 16 + (lane & 15);
        offA[mt] = rowA * 128;
        permA[mt] = (rowA & 7);
    }
    const unsigned halfA = lane >> 4;
    unsigned offB[4], permB[4];
    #pragma unroll
    for (int np = 0; np < 4; np++) {
        int rowB = warp_n * 64 + np * 16 + ((lane & 16) >> 1) + (lane & 7);
        offB[np] = A_BYTES + rowB * 128;
        permB[np] = (rowB & 7);
    }
    const unsigned halfB = (lane >> 3) & 1;

    float acc[4][8][4];
    #pragma unroll
    for (int mt = 0; mt < 4; mt++)
        #pragma unroll
        for (int nt = 0; nt < 8; nt++)
            #pragma unroll
            for (int c = 0; c < 4; c++) acc[mt][nt][c] = 0.f;

    // ---- stage issue helper ----
    auto issue = [&](int idx) {
        int jt  = idx / NCHUNK;
        int kc  = idx - jt * NCHUNK;
        int term = kc >> 2;
        int kbw  = (kc & 3) * 32 + lg_q * 4;
        const unsigned* Asrc = (term < 2) ? Ahi : Alo;
        const unsigned* Bsrc = (term == 1) ? Blo : Bhi;
        size_t jb = (size_t)jt * 256 * NWORDS;
        unsigned st = sb + (unsigned)(idx % STAGES) * STAGE_B;
        #pragma unroll
        for (int h = 0; h < 4; h++) {
            int r = lg_r + h * 32;
            CP_ASYNC16(st + r * 128 + swq,
                       __cvta_generic_to_global(Asrc + (size_t)(i0 + r) * NWORDS + kbw));
        }
        #pragma unroll
        for (int h = 0; h < 8; h++) {
            int r = lg_r + h * 32;
            CP_ASYNC16(st + A_BYTES + r * 128 + swq,
                       __cvta_generic_to_global(Bsrc + jb + (size_t)r * NWORDS + kbw));
        }
    };

    // prologue: stages 0,1 in flight
    issue(0); CP_COMMIT();
    issue(1); CP_COMMIT();

    for (int idx = 0; idx < TOTAL; idx++) {
        const int jt = idx / NCHUNK;
        const int kc = idx - jt * NCHUNK;

        CP_WAIT1();              // stage idx resident
        __syncthreads();         // all warps done with the buffer we overwrite next

        if (idx + 2 < TOTAL) { issue(idx + 2); CP_COMMIT(); }

        // ---- compute chunk idx: 4 k-steps of 16 ----
        const unsigned base = sb + (unsigned)(idx % STAGES) * STAGE_B;
        #pragma unroll
        for (int ks = 0; ks < 4; ks++) {
            unsigned a[4][4], b[4][4];
            #pragma unroll
            for (int mt = 0; mt < 4; mt++) {
                unsigned addr = base + offA[mt]
                              + (((2u * ks + halfA) ^ permA[mt]) << 4);
                LDSM_X4(a[mt][0], a[mt][1], a[mt][2], a[mt][3], addr);
            }
            #pragma unroll
            for (int np = 0; np < 4; np++) {
                unsigned addr = base + offB[np]
                              + (((2u * ks + halfB) ^ permB[np]) << 4);
                LDSM_X4(b[np][0], b[np][1], b[np][2], b[np][3], addr);
            }
            #pragma unroll
            for (int mt = 0; mt < 4; mt++) {
                #pragma unroll
                for (int np = 0; np < 4; np++) {
                    MMA16816(acc[mt][np * 2],     a[mt], b[np][0], b[np][1]);
                    MMA16816(acc[mt][np * 2 + 1], a[mt], b[np][2], b[np][3]);
                }
            }
        }

        // ---- end of j-tile: compare + fold ----
        if (kc == NCHUNK - 1) {
            int j0 = jt * 256 + warp_n * 64 + (lane & 3) * 2;
            #pragma unroll
            for (int mt = 0; mt < 4; mt++) {
                int ia = i0 + warp_m * 64 + mt * 16 + (lane >> 2);
                int ib = ia + 8;
                float da = dva[mt], db = dvb[mt];
                int ca = 0, cb = 0;
                #pragma unroll
                for (int nt = 0; nt < 8; nt++) {
                    int j = j0 + nt * 8;
                    float s0 = acc[mt][nt][0], s1 = acc[mt][nt][1];
                    float s2 = acc[mt][nt][2], s3 = acc[mt][nt][3];
                    ca += (j     != ia) && ((s0 > da) || (s0 == da && j     < ia));
                    ca += (j + 1 != ia) && ((s1 > da) || (s1 == da && j + 1 < ia));
                    cb += (j     != ib) && ((s2 > db) || (s2 == db && j     < ib));
                    cb += (j + 1 != ib) && ((s3 > db) || (s3 == db && j + 1 < ib));
                    acc[mt][nt][0] = 0.f; acc[mt][nt][1] = 0.f;
                    acc[mt][nt][2] = 0.f; acc[mt][nt][3] = 0.f;
                }
                cnt[mt][0] += ca;
                cnt[mt][1] += cb;
            }
        }
    }

    // ---- reduce counters ----
    __syncthreads();
    #pragma unroll
    for (int mt = 0; mt < 4; mt++) {
        int la = warp_m * 64 + mt * 16 + (lane >> 2);
        atomicAdd(&scnt[la], cnt[mt][0]);
        atomicAdd(&scnt[la + 8], cnt[mt][1]);
    }
    __syncthreads();
    if (t < 128) mrk[i0 + t] = (float)scnt[t];
}

// ---------------- 5. scalars -------------------------------------------------
__global__ void finalize_kernel(float* __restrict__ out) {
    __shared__ float red[256];
    int t = threadIdx.x;
    for (int m = 0; m < 4; m++) {
        float s = 0.f, q = 0.f;
        #pragma unroll 8
        for (int ch = 0; ch < 64; ch++) { s += g_cs[m][ch][t]; q += g_cq[m][ch][t]; }
        float var = (q - s * s / (float)NROWS) / (float)(NROWS - 1);
        red[t] = sqrtf(fmaxf(var, 0.f));
        __syncthreads();
        for (int off = 128; off; off >>= 1) {
            if (t < off) red[t] += red[t + off];
            __syncthreads();
        }
        if (t == 0) out[1 + m] = red[0] / (float)NC;
        __syncthreads();
    }
    float s1 = 0.f, s2 = 0.f;
    for (int i = t; i < NROWS; i += 256) { s1 += g_d1[i]; s2 += g_d2[i]; }
    red[t] = s1; __syncthreads();
    for (int off = 128; off; off >>= 1) { if (t < off) red[t] += red[t + off]; __syncthreads(); }
    float S1 = red[0]; __syncthreads();
    red[t] = s2; __syncthreads();
    for (int off = 128; off; off >>= 1) { if (t < off) red[t] += red[t + off]; __syncthreads(); }
    if (t == 0) {
        float S2 = red[0];
        out[0] = -0.5f * (S1 / (float)NROWS) - 0.5f * (S2 / (float)NROWS);
    }
}

// ---------------- 6. constant recall vectors --------------------------------
__global__ void fill_kernel(float* __restrict__ out) {
    int idx = blockIdx.x * 256 + threadIdx.x;
    if (idx >= 3 * NROWS) return;
    int r = idx / NROWS;
    float val = (r == 0) ? 1.0f : (r == 1) ? 5.0f : 10.0f;
    out[5 + idx] = val;
    out[5 + 4 * NROWS + idx] = val;
}

// ---------------- launch -----------------------------------------------------
extern "C" void kernel_launch(void* const* d_in, const int* in_sizes, int n_in,
                              void* d_out, int out_size) {
    const float* v  = (const float*)d_in[0];
    const float* t  = (const float*)d_in[1];
    const float* pv = (const float*)d_in[2];
    const float* pt = (const float*)d_in[3];
    float* out = (float*)d_out;

    cudaFuncSetAttribute(count_kernel,
                         cudaFuncAttributeMaxDynamicSharedMemorySize, DYN_SMEM);

    normalize_kernel<<<dim3(NROWS / 8, 4), 256>>>(v, t, pv, pt);
    colstats_kernel<<<dim3(64, 4), 256>>>();
    diag_kernel<<<dim3(NROWS / 8), 256>>>();
    count_kernel<<<dim3(64, 2), 256, DYN_SMEM>>>(out);
    finalize_kernel<<<1, 256>>>(out);
    fill_kernel<<<(3 * NROWS + 255) / 256, 256>>>(out);
}

// round 6
// speedup vs baseline: 1.3745x; 1.1826x over previous
#include <cuda_runtime.h>
#include <cuda_bf16.h>
#include <math.h>
#include <stdint.h>

#define NROWS 8192
#define NC    256
#define NWORDS (NC/2)          // 128 uint32 (bf16x2) per row

// ---------------- scratch ----------------------------------------------------
__device__ float    g_nrm[4][NROWS * NC];      // normalized fp32 (v,t,pv,pt)
__device__ unsigned g_bhi[4][NROWS * NWORDS];  // bf16 hi, packed bf16x2
__device__ unsigned g_blo[4][NROWS * NWORDS];  // bf16 lo, packed bf16x2
__device__ float    g_d1[NROWS];               // v_i . pt_i
__device__ float    g_d2[NROWS];               // t_i . pv_i
__device__ float    g_cs[4][64][NC];
__device__ float    g_cq[4][64][NC];
__device__ int      g_cnt[2][NROWS];           // global rank counters

// ---------------- small helpers ----------------------------------------------
__device__ __forceinline__ uint32_t smem_u32(const void* p) {
    uint32_t a;
    asm("{ .reg .u64 t; cvta.to.shared.u64 t, %1; cvt.u32.u64 %0, t; }"
        : "=r"(a) : "l"(p));
    return a;
}

#define CP_ASYNC16(dst, src)                                                   \
    asm volatile("cp.async.cg.shared.global [%0], [%1], 16;"                   \
                 :: "r"(dst), "l"(src) : "memory")
#define CP_COMMIT()  asm volatile("cp.async.commit_group;" ::: "memory")
#define CP_WAIT1()   asm volatile("cp.async.wait_group 1;" ::: "memory")

#define LDSM_X4(r0, r1, r2, r3, addr)                                          \
    asm volatile("ldmatrix.sync.aligned.m8n8.x4.shared.b16 {%0,%1,%2,%3}, [%4];" \
                 : "=r"(r0), "=r"(r1), "=r"(r2), "=r"(r3) : "r"(addr))

#define MMA16816(d, a, b0, b1)                                                 \
    asm volatile("mma.sync.aligned.m16n8k16.row.col.f32.bf16.bf16.f32 "        \
                 "{%0,%1,%2,%3}, {%4,%5,%6,%7}, {%8,%9}, {%0,%1,%2,%3};"       \
                 : "+f"((d)[0]), "+f"((d)[1]), "+f"((d)[2]), "+f"((d)[3])      \
                 : "r"((a)[0]), "r"((a)[1]), "r"((a)[2]), "r"((a)[3]),         \
                   "r"(b0), "r"(b1))

// ---------------- 1. normalize + bf16 hi/lo split ---------------------------
__device__ __forceinline__ unsigned pack2(__nv_bfloat16 a, __nv_bfloat16 b) {
    return (unsigned)__bfloat16_as_ushort(a) | ((unsigned)__bfloat16_as_ushort(b) << 16);
}
__device__ __forceinline__ void split_pair(float a, float b, unsigned& hi, unsigned& lo) {
    __nv_bfloat16 ha = __float2bfloat16_rn(a), hb = __float2bfloat16_rn(b);
    float ra = a - __bfloat162float(ha);
    float rb = b - __bfloat162float(hb);
    hi = pack2(ha, hb);
    lo = pack2(__float2bfloat16_rn(ra), __float2bfloat16_rn(rb));
}

__global__ void normalize_kernel(const float* __restrict__ v,
                                 const float* __restrict__ t,
                                 const float* __restrict__ pv,
                                 const float* __restrict__ pt) {
    int y = blockIdx.y;
    const float* src = (y == 0) ? v : (y == 1) ? t : (y == 2) ? pv : pt;
    int warp = threadIdx.x >> 5, lane = threadIdx.x & 31;
    int row = blockIdx.x * 8 + warp;
    const float4* s4 = (const float4*)(src + (size_t)row * NC);
    float4 x0 = s4[lane];
    float4 x1 = s4[lane + 32];
    float ss = x0.x*x0.x + x0.y*x0.y + x0.z*x0.z + x0.w*x0.w
             + x1.x*x1.x + x1.y*x1.y + x1.z*x1.z + x1.w*x1.w;
    #pragma unroll
    for (int o = 16; o; o >>= 1) ss += __shfl_xor_sync(0xffffffffu, ss, o);
    float r = 1.0f / fmaxf(sqrtf(ss), 1e-12f);
    x0.x *= r; x0.y *= r; x0.z *= r; x0.w *= r;
    x1.x *= r; x1.y *= r; x1.z *= r; x1.w *= r;
    float4* d4 = (float4*)(g_nrm[y] + (size_t)row * NC);
    d4[lane] = x0;
    d4[lane + 32] = x1;
    unsigned h, l;
    size_t rb = (size_t)row * NWORDS;
    split_pair(x0.x, x0.y, h, l); g_bhi[y][rb + 2*lane]      = h; g_blo[y][rb + 2*lane]      = l;
    split_pair(x0.z, x0.w, h, l); g_bhi[y][rb + 2*lane + 1]  = h; g_blo[y][rb + 2*lane + 1]  = l;
    split_pair(x1.x, x1.y, h, l); g_bhi[y][rb + 64 + 2*lane] = h; g_blo[y][rb + 64 + 2*lane] = l;
    split_pair(x1.z, x1.w, h, l); g_bhi[y][rb + 65 + 2*lane] = h; g_blo[y][rb + 65 + 2*lane] = l;
}

// ---------------- 2. per-column partial sums --------------------------------
__global__ void colstats_kernel() {
    const float* X = g_nrm[blockIdx.y];
    int col = threadIdx.x;
    int r0 = blockIdx.x * 128;
    float s = 0.f, q = 0.f;
    #pragma unroll 4
    for (int r = 0; r < 128; r++) {
        float x = X[(size_t)(r0 + r) * NC + col];
        s += x; q += x * x;
    }
    g_cs[blockIdx.y][blockIdx.x][col] = s;
    g_cq[blockIdx.y][blockIdx.x][col] = q;
}

// ---------------- 3. diagonals + zero count buffer --------------------------
__global__ void diag_kernel() {
    int warp = threadIdx.x >> 5, lane = threadIdx.x & 31;
    int row = blockIdx.x * 8 + warp;
    // zero the global counters (grid 1024 x 256 threads covers 2*8192 ints)
    int zi = blockIdx.x * 256 + threadIdx.x;
    if (zi < 2 * NROWS) ((int*)g_cnt)[zi] = 0;

    size_t base = (size_t)row * NC;
    const float4* a = (const float4*)(g_nrm[0] + base);
    const float4* b = (const float4*)(g_nrm[3] + base);
    const float4* c = (const float4*)(g_nrm[1] + base);
    const float4* d = (const float4*)(g_nrm[2] + base);
    float4 a0 = a[lane], a1 = a[lane+32], b0 = b[lane], b1 = b[lane+32];
    float4 c0 = c[lane], c1 = c[lane+32], d0 = d[lane], d1 = d[lane+32];
    float s1 = a0.x*b0.x + a0.y*b0.y + a0.z*b0.z + a0.w*b0.w
             + a1.x*b1.x + a1.y*b1.y + a1.z*b1.z + a1.w*b1.w;
    float s2 = c0.x*d0.x + c0.y*d0.y + c0.z*d0.z + c0.w*d0.w
             + c1.x*d1.x + c1.y*d1.y + c1.z*d1.z + c1.w*d1.w;
    #pragma unroll
    for (int o = 16; o; o >>= 1) {
        s1 += __shfl_xor_sync(0xffffffffu, s1, o);
        s2 += __shfl_xor_sync(0xffffffffu, s2, o);
    }
    if (lane == 0) { g_d1[row] = s1; g_d2[row] = s2; }
}

// ---------------- 4. HMMA GEMM + rank count ---------------------------------
// 3-term split GEMM, K'=768. BM=128, BN=128, BK=64. 128 threads, 4 warps (2x2),
// warp tile 64x64. 3-stage cp.async, 2 CTAs/SM, j-range split 4 ways.
#define A_BYTES  16384              // 128 rows x 128 B
#define B_BYTES  16384              // 128 rows x 128 B
#define STAGE_B  (A_BYTES + B_BYTES)
#define STAGES   3
#define DYN_SMEM (STAGES * STAGE_B + 1024)
#define NCHUNK   12                 // 768 / 64
#define JSPLIT   4
#define NJT      (64 / JSPLIT)      // 16 j-tiles of 128 per CTA
#define TOTAL    (NJT * NCHUNK)

__global__ void __launch_bounds__(128, 2) count_kernel() {
    extern __shared__ char dynsm[];
    __shared__ int scnt[128];

    const int t = threadIdx.x;
    const int lane = t & 31;
    const int wid = t >> 5;
    const int warp_m = wid & 1;          // 0..1 -> 64-row slab
    const int warp_n = wid >> 1;         // 0..1 -> 64-col slab
    const int mat = blockIdx.y;
    const int i0 = blockIdx.x * 128;
    const int jt0 = blockIdx.z * NJT;    // first j-tile (of 128 cols) for this CTA

    const unsigned* __restrict__ Ahi = g_bhi[mat ? 1 : 0];
    const unsigned* __restrict__ Alo = g_blo[mat ? 1 : 0];
    const unsigned* __restrict__ Bhi = g_bhi[mat ? 2 : 3];
    const unsigned* __restrict__ Blo = g_blo[mat ? 2 : 3];
    const float*    __restrict__ diag = mat ? g_d2 : g_d1;

    const unsigned sb = (smem_u32(dynsm) + 1023u) & ~1023u;

    if (t < 128) scnt[t] = 0;

    // loader: 128 threads. A: 128 rows (8/thread), B: 128 rows (8/thread), 16B each
    const int lg_r = t >> 3;             // 0..15
    const int lg_q = t & 7;              // 16B quad within 128B row
    const unsigned swq = ((unsigned)(lg_q ^ (lg_r & 7))) << 4;   // r+16k keeps r&7

    // per-thread diag values and counters
    float dva[4], dvb[4];
    #pragma unroll
    for (int mt = 0; mt < 4; mt++) {
        int ra = i0 + warp_m * 64 + mt * 16 + (lane >> 2);
        dva[mt] = diag[ra];
        dvb[mt] = diag[ra + 8];
    }
    int cnt[4][2];
    #pragma unroll
    for (int mt = 0; mt < 4; mt++) { cnt[mt][0] = 0; cnt[mt][1] = 0; }

    // ldmatrix address components (within a stage)
    unsigned offA[4], permA[4];
    #pragma unroll
    for (int mt = 0; mt < 4; mt++) {
        int rowA = warp_m * 64 + mt * 16 + (lane & 15);
        offA[mt] = rowA * 128;
        permA[mt] = (rowA & 7);
    }
    const unsigned halfA = lane >> 4;
    unsigned offB[4], permB[4];
    #pragma unroll
    for (int np = 0; np < 4; np++) {
        int rowB = warp_n * 64 + np * 16 + ((lane & 16) >> 1) + (lane & 7);
        offB[np] = A_BYTES + rowB * 128;
        permB[np] = (rowB & 7);
    }
    const unsigned halfB = (lane >> 3) & 1;

    float acc[4][8][4];
    #pragma unroll
    for (int mt = 0; mt < 4; mt++)
        #pragma unroll
        for (int nt = 0; nt < 8; nt++)
            #pragma unroll
            for (int c = 0; c < 4; c++) acc[mt][nt][c] = 0.f;

    // ---- stage issue helper ----
    auto issue = [&](int idx) {
        int jt  = idx / NCHUNK;
        int kc  = idx - jt * NCHUNK;
        int term = kc >> 2;
        int kbw  = (kc & 3) * 32 + lg_q * 4;
        const unsigned* Asrc = (term < 2) ? Ahi : Alo;
        const unsigned* Bsrc = (term == 1) ? Blo : Bhi;
        size_t jb = (size_t)(jt0 + jt) * 128 * NWORDS;
        unsigned st = sb + (unsigned)(idx % STAGES) * STAGE_B;
        #pragma unroll
        for (int h = 0; h < 8; h++) {
            int r = lg_r + h * 16;
            CP_ASYNC16(st + r * 128 + swq,
                       __cvta_generic_to_global(Asrc + (size_t)(i0 + r) * NWORDS + kbw));
            CP_ASYNC16(st + A_BYTES + r * 128 + swq,
                       __cvta_generic_to_global(Bsrc + jb + (size_t)r * NWORDS + kbw));
        }
    };

    // prologue: stages 0,1 in flight
    issue(0); CP_COMMIT();
    issue(1); CP_COMMIT();

    for (int idx = 0; idx < TOTAL; idx++) {
        const int jt = idx / NCHUNK;
        const int kc = idx - jt * NCHUNK;

        CP_WAIT1();              // stage idx resident
        __syncthreads();         // all warps done with the buffer we overwrite next

        if (idx + 2 < TOTAL) { issue(idx + 2); CP_COMMIT(); }

        // ---- compute chunk idx: 4 k-steps of 16 ----
        const unsigned base = sb + (unsigned)(idx % STAGES) * STAGE_B;
        #pragma unroll
        for (int ks = 0; ks < 4; ks++) {
            unsigned a[4][4], b[4][4];
            #pragma unroll
            for (int mt = 0; mt < 4; mt++) {
                unsigned addr = base + offA[mt]
                              + (((2u * ks + halfA) ^ permA[mt]) << 4);
                LDSM_X4(a[mt][0], a[mt][1], a[mt][2], a[mt][3], addr);
            }
            #pragma unroll
            for (int np = 0; np < 4; np++) {
                unsigned addr = base + offB[np]
                              + (((2u * ks + halfB) ^ permB[np]) << 4);
                LDSM_X4(b[np][0], b[np][1], b[np][2], b[np][3], addr);
            }
            #pragma unroll
            for (int mt = 0; mt < 4; mt++) {
                #pragma unroll
                for (int np = 0; np < 4; np++) {
                    MMA16816(acc[mt][np * 2],     a[mt], b[np][0], b[np][1]);
                    MMA16816(acc[mt][np * 2 + 1], a[mt], b[np][2], b[np][3]);
                }
            }
        }

        // ---- end of j-tile: compare + fold ----
        if (kc == NCHUNK - 1) {
            int j0 = (jt0 + jt) * 128 + warp_n * 64 + (lane & 3) * 2;
            #pragma unroll
            for (int mt = 0; mt < 4; mt++) {
                int ia = i0 + warp_m * 64 + mt * 16 + (lane >> 2);
                int ib = ia + 8;
                float da = dva[mt], db = dvb[mt];
                int ca = 0, cb = 0;
                #pragma unroll
                for (int nt = 0; nt < 8; nt++) {
                    int j = j0 + nt * 8;
                    float s0 = acc[mt][nt][0], s1 = acc[mt][nt][1];
                    float s2 = acc[mt][nt][2], s3 = acc[mt][nt][3];
                    ca += (j     != ia) && ((s0 > da) || (s0 == da && j     < ia));
                    ca += (j + 1 != ia) && ((s1 > da) || (s1 == da && j + 1 < ia));
                    cb += (j     != ib) && ((s2 > db) || (s2 == db && j     < ib));
                    cb += (j + 1 != ib) && ((s3 > db) || (s3 == db && j + 1 < ib));
                    acc[mt][nt][0] = 0.f; acc[mt][nt][1] = 0.f;
                    acc[mt][nt][2] = 0.f; acc[mt][nt][3] = 0.f;
                }
                cnt[mt][0] += ca;
                cnt[mt][1] += cb;
            }
        }
    }

    // ---- reduce counters: shared, then one global atomic per row ----
    __syncthreads();
    #pragma unroll
    for (int mt = 0; mt < 4; mt++) {
        int la = warp_m * 64 + mt * 16 + (lane >> 2);
        atomicAdd(&scnt[la], cnt[mt][0]);
        atomicAdd(&scnt[la + 8], cnt[mt][1]);
    }
    __syncthreads();
    if (t < 128) atomicAdd(&g_cnt[mat][i0 + t], scnt[t]);
}

// ---------------- 5. scalars -------------------------------------------------
__global__ void finalize_kernel(float* __restrict__ out) {
    __shared__ float red[256];
    int t = threadIdx.x;
    for (int m = 0; m < 4; m++) {
        float s = 0.f, q = 0.f;
        #pragma unroll 8
        for (int ch = 0; ch < 64; ch++) { s += g_cs[m][ch][t]; q += g_cq[m][ch][t]; }
        float var = (q - s * s / (float)NROWS) / (float)(NROWS - 1);
        red[t] = sqrtf(fmaxf(var, 0.f));
        __syncthreads();
        for (int off = 128; off; off >>= 1) {
            if (t < off) red[t] += red[t + off];
            __syncthreads();
        }
        if (t == 0) out[1 + m] = red[0] / (float)NC;
        __syncthreads();
    }
    float s1 = 0.f, s2 = 0.f;
    for (int i = t; i < NROWS; i += 256) { s1 += g_d1[i]; s2 += g_d2[i]; }
    red[t] = s1; __syncthreads();
    for (int off = 128; off; off >>= 1) { if (t < off) red[t] += red[t + off]; __syncthreads(); }
    float S1 = red[0]; __syncthreads();
    red[t] = s2; __syncthreads();
    for (int off = 128; off; off >>= 1) { if (t < off) red[t] += red[t + off]; __syncthreads(); }
    if (t == 0) {
        float S2 = red[0];
        out[0] = -0.5f * (S1 / (float)NROWS) - 0.5f * (S2 / (float)NROWS);
    }
}

// ---------------- 6. recall constants + mean_rk writeback --------------------
__global__ void fill_kernel(float* __restrict__ out) {
    int idx = blockIdx.x * 256 + threadIdx.x;
    if (idx < 3 * NROWS) {
        int r = idx / NROWS;
        float val = (r == 0) ? 1.0f : (r == 1) ? 5.0f : 10.0f;
        out[5 + idx] = val;                 // v_r1 / v_r5 / v_r10
        out[5 + 4 * NROWS + idx] = val;     // t_r1 / t_r5 / t_r10
    }
    if (idx < 2 * NROWS) {
        int m = idx / NROWS, i = idx - m * NROWS;
        out[5 + (size_t)(m ? 7 : 3) * NROWS + i] = (float)g_cnt[m][i];
    }
}

// ---------------- launch -----------------------------------------------------
extern "C" void kernel_launch(void* const* d_in, const int* in_sizes, int n_in,
                              void* d_out, int out_size) {
    const float* v  = (const float*)d_in[0];
    const float* t  = (const float*)d_in[1];
    const float* pv = (const float*)d_in[2];
    const float* pt = (const float*)d_in[3];
    float* out = (float*)d_out;

    cudaFuncSetAttribute(count_kernel,
                         cudaFuncAttributeMaxDynamicSharedMemorySize, DYN_SMEM);

    normalize_kernel<<<dim3(NROWS / 8, 4), 256>>>(v, t, pv, pt);
    colstats_kernel<<<dim3(64, 4), 256>>>();
    diag_kernel<<<dim3(NROWS / 8), 256>>>();
    count_kernel<<<dim3(64, 2, JSPLIT), 128, DYN_SMEM>>>();
    finalize_kernel<<<1, 256>>>(out);
    fill_kernel<<<(3 * NROWS + 255) / 256, 256>>>(out);
}